// round 12
// baseline (speedup 1.0000x reference)
#include <cuda_runtime.h>
#include <cuda_bf16.h>

// Problem constants
#define NB    2
#define CCH   512
#define SSP   4096     // 64*64 spatial tokens
#define NH    8
#define HD    64
#define NHTOT (NB*NH)  // 16

// Q pre-scale: 1/sqrt(64) * log2(e)  (scores come out in log2 units)
#define QSCALE 0.18033688011f

// ---------------- scratch (static __device__, no allocations) ----------------
__device__ __align__(16) unsigned short g_xT[NB*SSP*CCH];   // x^T bf16, token-major [n][s][c]
__device__ __align__(16) unsigned short g_W [4*CCH*CCH];    // Wq,Wk,Wv,Wo bf16 [o][c]
__device__ __align__(16) unsigned short g_Qt[NHTOT*SSP*HD]; // [n*8+h][s][d] (pre-scaled)
__device__ __align__(16) unsigned short g_Kt[NHTOT*SSP*HD]; // [n*8+h][s][d]
__device__ __align__(16) unsigned short g_Vc[NB*CCH*SSP];   // [n][c][s] (c = h*64+d)
__device__ __align__(16) unsigned short g_Ot[NB*SSP*CCH];   // attn out token-major [n][s][c]

// ---------------- helpers ----------------
__device__ __forceinline__ unsigned short f2bf(float v) {
    __nv_bfloat16 h = __float2bfloat16(v);
    return *reinterpret_cast<unsigned short*>(&h);
}
__device__ __forceinline__ unsigned pk2(float a, float b) {
    __nv_bfloat162 t = __floats2bfloat162_rn(a, b);
    return *reinterpret_cast<unsigned*>(&t);
}
__device__ __forceinline__ float ex2(float x) {
    float y;
    asm("ex2.approx.ftz.f32 %0, %1;" : "=f"(y) : "f"(x));
    return y;
}
__device__ __forceinline__ unsigned smem_u32(const void* p) {
    return (unsigned)__cvta_generic_to_shared(p);
}
__device__ __forceinline__ void cpasync16(unsigned dst, const void* src) {
    asm volatile("cp.async.cg.shared.global [%0], [%1], 16;\n" :: "r"(dst), "l"(src));
}
__device__ __forceinline__ void cpcommit() {
    asm volatile("cp.async.commit_group;\n" ::: "memory");
}
template<int N> __device__ __forceinline__ void cpwait() {
    asm volatile("cp.async.wait_group %0;\n" :: "n"(N) : "memory");
}
__device__ __forceinline__ void ldsm_x4(unsigned& r0, unsigned& r1, unsigned& r2,
                                        unsigned& r3, unsigned addr) {
    asm volatile("ldmatrix.sync.aligned.m8n8.x4.shared.b16 {%0,%1,%2,%3}, [%4];"
        : "=r"(r0), "=r"(r1), "=r"(r2), "=r"(r3) : "r"(addr));
}
// D += A*B, m16n8k16 bf16 -> f32
__device__ __forceinline__ void mma16816(float* c,
        unsigned a0, unsigned a1, unsigned a2, unsigned a3,
        unsigned b0, unsigned b1) {
    asm volatile(
        "mma.sync.aligned.m16n8k16.row.col.f32.bf16.bf16.f32 "
        "{%0,%1,%2,%3},{%4,%5,%6,%7},{%8,%9},{%0,%1,%2,%3};\n"
        : "+f"(c[0]), "+f"(c[1]), "+f"(c[2]), "+f"(c[3])
        : "r"(a0), "r"(a1), "r"(a2), "r"(a3), "r"(b0), "r"(b1));
}

// ---------------- K0a: weights fp32 -> bf16 ----------------
__global__ void convw_kernel(const float* __restrict__ wq, const float* __restrict__ wk,
                             const float* __restrict__ wv, const float* __restrict__ wo) {
    int stride = gridDim.x * blockDim.x;
    int t0 = blockIdx.x * blockDim.x + threadIdx.x;
    const int WSZ = CCH*CCH;
    for (int i = t0; i < WSZ; i += stride) {
        g_W[i]         = f2bf(wq[i]);
        g_W[WSZ + i]   = f2bf(wk[i]);
        g_W[2*WSZ + i] = f2bf(wv[i]);
        g_W[3*WSZ + i] = f2bf(wo[i]);
    }
}

// ---------------- K0b: x [n][c][s] fp32 -> x^T [n][s][c] bf16 ----------------
__global__ void transpose_kernel(const float* __restrict__ x) {
    __shared__ float t[32][33];
    int n = blockIdx.z;
    int s0 = blockIdx.x * 32, c0 = blockIdx.y * 32;
    int tx = threadIdx.x, ty = threadIdx.y;   // 32 x 8
    const float* src = x + ((size_t)n*CCH + c0)*SSP + s0;
    #pragma unroll
    for (int k = 0; k < 4; k++)
        t[ty + 8*k][tx] = src[(size_t)(ty + 8*k)*SSP + tx];
    __syncthreads();
    unsigned short* dst = g_xT + ((size_t)n*SSP + s0)*CCH + c0;
    #pragma unroll
    for (int k = 0; k < 4; k++)
        dst[(size_t)(ty + 8*k)*CCH + tx] = f2bf(t[tx][ty + 8*k]);
}

// ---------------- K1/K3: tiled GEMM, all operands K-major (stride-512 rows) ----------------
#define GSTAGE 32768
#define G_SMEM (3*GSTAGE)
__global__ __launch_bounds__(256,2) void gemm_kernel(int phase,
        const float* __restrict__ bq, const float* __restrict__ bk,
        const float* __restrict__ bv, const float* __restrict__ bo,
        const float* __restrict__ x, const float* __restrict__ gamma,
        float* __restrict__ out) {
    extern __shared__ __align__(1024) unsigned char gsm[];
    unsigned smb = smem_u32(gsm);

    int which, n;
    if (phase == 0) { int z = blockIdx.z; which = z >> 1; n = z & 1; }
    else            { which = 3; n = blockIdx.z; }

    int tid = threadIdx.x;
    int sBase = blockIdx.x * 128;   // token-tile
    int oBase = blockIdx.y * 128;   // output-channel tile
    const unsigned short* xTn = g_xT + (size_t)n * SSP * CCH;
    const unsigned short* Am;
    const unsigned short* Bm;
    if (which <= 1) {
        Am = xTn + (size_t)sBase*CCH;
        Bm = g_W + (size_t)which*CCH*CCH + (size_t)oBase*CCH;
    } else if (which == 2) {
        Am = g_W + 2*(size_t)CCH*CCH + (size_t)oBase*CCH;
        Bm = xTn + (size_t)sBase*CCH;
    } else {
        Am = g_W + 3*(size_t)CCH*CCH + (size_t)oBase*CCH;
        Bm = g_Ot + (size_t)n*SSP*CCH + (size_t)sBase*CCH;
    }

    int warp = tid >> 5, lane = tid & 31, g = lane >> 2, qi = lane & 3;
    int wm = warp >> 1, wn = warp & 1;
    int lq  = (lane & 7) + 8*((lane >> 3) & 1);
    int lc  = 8*(lane >> 4);
    int lq2 = (lane & 7) + 8*(lane >> 4);
    int lc2 = 8*((lane >> 3) & 1);

    auto sw = [](int r, int k) -> unsigned {
        return (unsigned)(r*128 + ((2*k) ^ ((r & 7) << 4)));
    };

    float acc[2][8][4];
    #pragma unroll
    for (int a = 0; a < 2; a++)
        #pragma unroll
        for (int b = 0; b < 8; b++)
            #pragma unroll
            for (int c = 0; c < 4; c++) acc[a][b][c] = 0.f;

    auto stage = [&](int s) {
        unsigned ab = smb + (unsigned)(s % 3) * (unsigned)GSTAGE;
        unsigned bb = ab + 16384u;
        int kc = s * 64;
        #pragma unroll
        for (int j = 0; j < 4; j++) {
            int u = tid + j*256;
            int r = u >> 3, ck = (u & 7) * 8;
            cpasync16(ab + sw(r, ck), &Am[(size_t)r*CCH + kc + ck]);
            cpasync16(bb + sw(r, ck), &Bm[(size_t)r*CCH + kc + ck]);
        }
        cpcommit();
    };

    stage(0);
    stage(1);

    for (int s = 0; s < 8; s++) {
        if (s < 7) cpwait<1>(); else cpwait<0>();
        __syncthreads();
        if (s + 2 < 8) stage(s + 2);

        unsigned ab = smb + (unsigned)(s % 3) * (unsigned)GSTAGE;
        unsigned bb = ab + 16384u;
        #pragma unroll
        for (int ks = 0; ks < 4; ks++) {
            int k0 = ks * 16;
            unsigned af[2][4], bf[8][2];
            #pragma unroll
            for (int mt = 0; mt < 2; mt++)
                ldsm_x4(af[mt][0], af[mt][1], af[mt][2], af[mt][3],
                        ab + sw(wm*32 + mt*16 + lq, k0 + lc));
            #pragma unroll
            for (int ng = 0; ng < 4; ng++) {
                unsigned r0, r1, r2, r3;
                ldsm_x4(r0, r1, r2, r3,
                        bb + sw(wn*64 + ng*16 + lq2, k0 + lc2));
                bf[2*ng][0] = r0;  bf[2*ng][1] = r1;
                bf[2*ng+1][0] = r2; bf[2*ng+1][1] = r3;
            }
            #pragma unroll
            for (int mt = 0; mt < 2; mt++)
                #pragma unroll
                for (int nt = 0; nt < 8; nt++)
                    mma16816(acc[mt][nt], af[mt][0], af[mt][1], af[mt][2], af[mt][3],
                             bf[nt][0], bf[nt][1]);
        }
    }

    // ---------------- epilogue ----------------
    if (which <= 1) {
        const float* bias = (which == 0) ? bq : bk;
        unsigned short* dst = (which == 0) ? g_Qt : g_Kt;
        float qs = (which == 0) ? QSCALE : 1.0f;
        #pragma unroll
        for (int nt = 0; nt < 8; nt++) {
            int c = oBase + wn*64 + nt*8 + 2*qi;
            float b0 = bias[c], b1 = bias[c + 1];
            int h = c >> 6, d = c & 63;
            unsigned short* dh = dst + (size_t)(n*8 + h)*(SSP*HD) + d;
            #pragma unroll
            for (int mt = 0; mt < 2; mt++) {
                int r0 = sBase + wm*32 + mt*16 + g;
                *(unsigned*)&dh[(size_t) r0      *HD] =
                    pk2((acc[mt][nt][0] + b0)*qs, (acc[mt][nt][1] + b1)*qs);
                *(unsigned*)&dh[(size_t)(r0 + 8) *HD] =
                    pk2((acc[mt][nt][2] + b0)*qs, (acc[mt][nt][3] + b1)*qs);
            }
        }
    } else if (which == 2) {
        #pragma unroll
        for (int mt = 0; mt < 2; mt++) {
            int o0 = oBase + wm*32 + mt*16 + g;
            int o1 = o0 + 8;
            float b0 = bv[o0], b1 = bv[o1];
            #pragma unroll
            for (int nt = 0; nt < 8; nt++) {
                int s = sBase + wn*64 + nt*8 + 2*qi;
                unsigned short* d0p = g_Vc + ((size_t)n*CCH + o0) * SSP;
                unsigned short* d1p = g_Vc + ((size_t)n*CCH + o1) * SSP;
                *(unsigned*)&d0p[s] = pk2(acc[mt][nt][0] + b0, acc[mt][nt][1] + b0);
                *(unsigned*)&d1p[s] = pk2(acc[mt][nt][2] + b1, acc[mt][nt][3] + b1);
            }
        }
    } else {
        float gm = gamma[0];
        #pragma unroll
        for (int mt = 0; mt < 2; mt++) {
            int o0 = oBase + wm*32 + mt*16 + g;
            int o1 = o0 + 8;
            float b0 = bo[o0], b1 = bo[o1];
            #pragma unroll
            for (int nt = 0; nt < 8; nt++) {
                int s = sBase + wn*64 + nt*8 + 2*qi;
                size_t i0 = ((size_t)n*CCH + o0) * SSP + s;
                size_t i1 = ((size_t)n*CCH + o1) * SSP + s;
                out[i0]     = gm * (acc[mt][nt][0] + b0) + x[i0];
                out[i0 + 1] = gm * (acc[mt][nt][1] + b0) + x[i0 + 1];
                out[i1]     = gm * (acc[mt][nt][2] + b1) + x[i1];
                out[i1 + 1] = gm * (acc[mt][nt][3] + b1) + x[i1 + 1];
            }
        }
    }
}

// ---------------- K2: flash attention, Br=128, Bc=128/stage ----------------
// 2D warp split: 4 row-groups (32 Q-rows) x 2 col-groups (32 t-cols) -> each
// K/V ldsm feeds 4 MMAs (shared-BW cut 36->24 ldsm per warp-half).
// Q pre-scaled (log2 units); no running max; row sums scalar (f32).
// Partial O / row-sums reduced across col-groups via smem at the end.
#define FL_SMEM (16384 + 3*32768)
__global__ __launch_bounds__(256,2) void flash_kernel() {
    extern __shared__ __align__(1024) unsigned char smarr[];
    unsigned qb = smem_u32(smarr);
    unsigned kv = qb + 16384;   // stage s at kv + (s%3)*32768: [K0 8K | K1 8K | V0 8K | V1 8K]

    int tid = threadIdx.x;
    int nh = blockIdx.y;            // n*8 + h
    int s0 = blockIdx.x * 128;
    const unsigned short* Qg = g_Qt + (size_t)nh * (SSP*HD);
    const unsigned short* Kg = g_Kt + (size_t)nh * (SSP*HD);
    const unsigned short* Vg = g_Vc + (size_t)nh * (HD*SSP);

    int warp = tid >> 5, lane = tid & 31, g = lane >> 2, qi = lane & 3;
    int wr = warp & 3, wc = warp >> 2;
    int R0 = wr * 32;               // Q-row base for this warp
    int C0 = wc * 32;               // t-col base within 64-col half
    int lq  = (lane & 7) + 8*((lane >> 3) & 1);
    int lc  = 8*(lane >> 4);
    int lq2 = (lane & 7) + 8*(lane >> 4);
    int lc2 = 8*((lane >> 3) & 1);

    auto sw = [](int row, int ch) -> unsigned {
        return (unsigned)(row*128 + ((ch*2) ^ ((row & 7) << 4)));
    };

    auto stageld = [&](int s) {
        unsigned sb = kv + (unsigned)(s % 3) * 32768u;
        int t0 = s * 128;
        #pragma unroll
        for (int r = 0; r < 2; r++) {
            int u = tid + r*256; int row = u >> 3, c = (u & 7) * 8;
            cpasync16(sb +          sw(row, c), &Kg[(size_t)(t0 + row)*HD + c]);
            cpasync16(sb + 8192u  + sw(row, c), &Kg[(size_t)(t0 + 64 + row)*HD + c]);
            cpasync16(sb + 16384u + sw(row, c), &Vg[(size_t)row*SSP + t0 + c]);
            cpasync16(sb + 24576u + sw(row, c), &Vg[(size_t)row*SSP + t0 + 64 + c]);
        }
        cpcommit();
    };

    // prologue: Q + stage0 in group 0, stage1 in group 1
    #pragma unroll
    for (int r = 0; r < 4; r++) {
        int u = tid + r*256; int row = u >> 3, c = (u & 7) * 8;
        cpasync16(qb + sw(row, c), &Qg[(size_t)(s0 + row)*HD + c]);
    }
    stageld(0);
    stageld(1);

    float ps[4];                      // partial row sums: [mt*2 + upper8]
    ps[0] = ps[1] = ps[2] = ps[3] = 0.f;
    float o[2][8][4];                 // O partial: [mt][nt][e], 32 rows x 64 d
    #pragma unroll
    for (int a = 0; a < 2; a++)
        #pragma unroll
        for (int b = 0; b < 8; b++)
            #pragma unroll
            for (int c = 0; c < 4; c++) o[a][b][c] = 0.f;

    for (int it = 0; it < 32; it++) {
        unsigned sb = kv + (unsigned)(((unsigned)it) % 3u) * 32768u;
        if (it < 31) cpwait<1>(); else cpwait<0>();
        __syncthreads();
        if (it + 2 < 32) stageld(it + 2);

        #pragma unroll
        for (int hlf = 0; hlf < 2; hlf++) {
            unsigned kb = sb + (unsigned)hlf * 8192u;
            unsigned vb = sb + 16384u + (unsigned)hlf * 8192u;

            // S[32r][32c] = Q @ K^T (log2 units): scf[np][nt][mt][e]
            float scf[2][2][2][4];
            #pragma unroll
            for (int np = 0; np < 2; np++)
                #pragma unroll
                for (int nt = 0; nt < 2; nt++)
                    #pragma unroll
                    for (int mt = 0; mt < 2; mt++)
                        #pragma unroll
                        for (int e = 0; e < 4; e++) scf[np][nt][mt][e] = 0.f;

            #pragma unroll
            for (int kk = 0; kk < 4; kk++) {
                unsigned qa[2][4];
                #pragma unroll
                for (int mt = 0; mt < 2; mt++)
                    ldsm_x4(qa[mt][0], qa[mt][1], qa[mt][2], qa[mt][3],
                            qb + sw(R0 + mt*16 + lq, kk*16 + lc));
                #pragma unroll
                for (int np = 0; np < 2; np++) {
                    unsigned r0, r1, r2, r3;
                    ldsm_x4(r0, r1, r2, r3, kb + sw(C0 + np*16 + lq2, kk*16 + lc2));
                    mma16816(scf[np][0][0], qa[0][0], qa[0][1], qa[0][2], qa[0][3], r0, r1);
                    mma16816(scf[np][1][0], qa[0][0], qa[0][1], qa[0][2], qa[0][3], r2, r3);
                    mma16816(scf[np][0][1], qa[1][0], qa[1][1], qa[1][2], qa[1][3], r0, r1);
                    mma16816(scf[np][1][1], qa[1][0], qa[1][1], qa[1][2], qa[1][3], r2, r3);
                }
            }

            // p = 2^s ; accumulate partial row sums (f32, fma pipe)
            #pragma unroll
            for (int np = 0; np < 2; np++)
                #pragma unroll
                for (int nt = 0; nt < 2; nt++)
                    #pragma unroll
                    for (int mt = 0; mt < 2; mt++) {
                        float* sv = scf[np][nt][mt];
                        sv[0] = ex2(sv[0]); sv[1] = ex2(sv[1]);
                        sv[2] = ex2(sv[2]); sv[3] = ex2(sv[3]);
                        ps[mt*2]     += sv[0] + sv[1];
                        ps[mt*2 + 1] += sv[2] + sv[3];
                    }

            // O += P @ V  (V fragment feeds 4 MMAs: both mt)
            #pragma unroll
            for (int kt = 0; kt < 2; kt++) {
                unsigned aP[2][4];
                #pragma unroll
                for (int mt = 0; mt < 2; mt++) {
                    aP[mt][0] = pk2(scf[kt][0][mt][0], scf[kt][0][mt][1]);
                    aP[mt][1] = pk2(scf[kt][0][mt][2], scf[kt][0][mt][3]);
                    aP[mt][2] = pk2(scf[kt][1][mt][0], scf[kt][1][mt][1]);
                    aP[mt][3] = pk2(scf[kt][1][mt][2], scf[kt][1][mt][3]);
                }
                #pragma unroll
                for (int ng = 0; ng < 4; ng++) {
                    unsigned r0, r1, r2, r3;
                    ldsm_x4(r0, r1, r2, r3, vb + sw(ng*16 + lq2, C0 + kt*16 + lc2));
                    mma16816(o[0][2*ng],     aP[0][0], aP[0][1], aP[0][2], aP[0][3], r0, r1);
                    mma16816(o[0][2*ng + 1], aP[0][0], aP[0][1], aP[0][2], aP[0][3], r2, r3);
                    mma16816(o[1][2*ng],     aP[1][0], aP[1][1], aP[1][2], aP[1][3], r0, r1);
                    mma16816(o[1][2*ng + 1], aP[1][0], aP[1][1], aP[1][2], aP[1][3], r2, r3);
                }
            }
        }
    }

    // ---- reduce partial O / ps across the 2 col-groups via smem ----
    __syncthreads();                       // all stage reads done; smem reusable
    float* redo = (float*)smarr;           // (wr*32+lane)*65 + i, conflict-free
    float* redp = (float*)(smarr + 34816); // (wr*32+lane)*4 + j
    if (wc == 1) {
        int base = (wr*32 + lane) * 65;
        const float* of = (const float*)o;
        #pragma unroll
        for (int i = 0; i < 64; i++) redo[base + i] = of[i];
        int pb = (wr*32 + lane) * 4;
        #pragma unroll
        for (int j = 0; j < 4; j++) redp[pb + j] = ps[j];
    }
    __syncthreads();
    if (wc == 0) {
        int base = (wr*32 + lane) * 65;
        float* of = (float*)o;
        #pragma unroll
        for (int i = 0; i < 64; i++) of[i] += redo[base + i];
        int pb = (wr*32 + lane) * 4;
        #pragma unroll
        for (int j = 0; j < 4; j++) ps[j] += redp[pb + j];
        // complete row sums across the 4 qi lanes of each row group
        #pragma unroll
        for (int j = 0; j < 4; j++) {
            ps[j] += __shfl_xor_sync(0xffffffffu, ps[j], 1);
            ps[j] += __shfl_xor_sync(0xffffffffu, ps[j], 2);
        }
        float inv[4];
        #pragma unroll
        for (int j = 0; j < 4; j++) inv[j] = 1.f / ps[j];

        // store normalized O token-major [n][s][c]
        int nn = nh >> 3, h = nh & 7;
        unsigned short* Og = g_Ot + ((size_t)nn*SSP + s0)*CCH + h*64;
        #pragma unroll
        for (int mt = 0; mt < 2; mt++) {
            int r0w = R0 + mt*16 + g, r1w = r0w + 8;
            #pragma unroll
            for (int nt = 0; nt < 8; nt++) {
                int dv = nt*8 + 2*qi;
                *(unsigned*)&Og[(size_t)r0w*CCH + dv] =
                    pk2(o[mt][nt][0]*inv[mt*2],     o[mt][nt][1]*inv[mt*2]);
                *(unsigned*)&Og[(size_t)r1w*CCH + dv] =
                    pk2(o[mt][nt][2]*inv[mt*2 + 1], o[mt][nt][3]*inv[mt*2 + 1]);
            }
        }
    }
}

// ---------------- launch ----------------
extern "C" void kernel_launch(void* const* d_in, const int* in_sizes, int n_in,
                              void* d_out, int out_size) {
    const float* x     = (const float*)d_in[0];
    const float* Wq    = (const float*)d_in[1];
    const float* bq    = (const float*)d_in[2];
    const float* Wk    = (const float*)d_in[3];
    const float* bk    = (const float*)d_in[4];
    const float* Wv    = (const float*)d_in[5];
    const float* bv    = (const float*)d_in[6];
    const float* Wo    = (const float*)d_in[7];
    const float* bo    = (const float*)d_in[8];
    const float* gamma = (const float*)d_in[9];
    float* out = (float*)d_out;

    cudaFuncSetAttribute(flash_kernel,
        cudaFuncAttributeMaxDynamicSharedMemorySize, FL_SMEM);
    cudaFuncSetAttribute(gemm_kernel,
        cudaFuncAttributeMaxDynamicSharedMemorySize, G_SMEM);

    convw_kernel<<<512, 256>>>(Wq, Wk, Wv, Wo);
    transpose_kernel<<<dim3(SSP/32, CCH/32, NB), dim3(32, 8)>>>(x);
    gemm_kernel<<<dim3(SSP/128, CCH/128, 6), 256, G_SMEM>>>(0, bq, bk, bv, bo, x, gamma, out);
    flash_kernel<<<dim3(SSP/128, NHTOT), 256, FL_SMEM>>>();
    gemm_kernel<<<dim3(SSP/128, CCH/128, NB), 256, G_SMEM>>>(1, bq, bk, bv, bo, x, gamma, out);
}

// round 13
// speedup vs baseline: 1.6045x; 1.6045x over previous
#include <cuda_runtime.h>
#include <cuda_bf16.h>

// Problem constants
#define NB    2
#define CCH   512
#define SSP   4096     // 64*64 spatial tokens
#define NH    8
#define HD    64
#define NHTOT (NB*NH)  // 16

// Q pre-scale: 1/sqrt(64) * log2(e)  (scores come out in log2 units)
#define QSCALE 0.18033688011f
// bf16 1.0 pair (ones B-fragment for row-sum MMA)
#define ONES2  0x3F803F80u

// ---------------- scratch (static __device__, no allocations) ----------------
__device__ __align__(16) unsigned short g_xT[NB*SSP*CCH];   // x^T bf16, token-major [n][s][c]
__device__ __align__(16) unsigned short g_W [4*CCH*CCH];    // Wq,Wk,Wv,Wo bf16 [o][c]
__device__ __align__(16) unsigned short g_Qt[NHTOT*SSP*HD]; // [n*8+h][s][d] (pre-scaled)
__device__ __align__(16) unsigned short g_Kt[NHTOT*SSP*HD]; // [n*8+h][s][d]
__device__ __align__(16) unsigned short g_Vc[NB*CCH*SSP];   // [n][c][s] (c = h*64+d)
__device__ __align__(16) unsigned short g_Ot[NB*SSP*CCH];   // attn out token-major [n][s][c]

// ---------------- helpers ----------------
__device__ __forceinline__ unsigned short f2bf(float v) {
    __nv_bfloat16 h = __float2bfloat16(v);
    return *reinterpret_cast<unsigned short*>(&h);
}
__device__ __forceinline__ unsigned pk2(float a, float b) {
    __nv_bfloat162 t = __floats2bfloat162_rn(a, b);
    return *reinterpret_cast<unsigned*>(&t);
}
__device__ __forceinline__ float ex2(float x) {
    float y;
    asm("ex2.approx.ftz.f32 %0, %1;" : "=f"(y) : "f"(x));
    return y;
}
__device__ __forceinline__ unsigned smem_u32(const void* p) {
    return (unsigned)__cvta_generic_to_shared(p);
}
__device__ __forceinline__ void cpasync16(unsigned dst, const void* src) {
    asm volatile("cp.async.cg.shared.global [%0], [%1], 16;\n" :: "r"(dst), "l"(src));
}
__device__ __forceinline__ void cpcommit() {
    asm volatile("cp.async.commit_group;\n" ::: "memory");
}
template<int N> __device__ __forceinline__ void cpwait() {
    asm volatile("cp.async.wait_group %0;\n" :: "n"(N) : "memory");
}
__device__ __forceinline__ void ldsm_x4(unsigned& r0, unsigned& r1, unsigned& r2,
                                        unsigned& r3, unsigned addr) {
    asm volatile("ldmatrix.sync.aligned.m8n8.x4.shared.b16 {%0,%1,%2,%3}, [%4];"
        : "=r"(r0), "=r"(r1), "=r"(r2), "=r"(r3) : "r"(addr));
}
// D += A*B, m16n8k16 bf16 -> f32
__device__ __forceinline__ void mma16816(float* c,
        unsigned a0, unsigned a1, unsigned a2, unsigned a3,
        unsigned b0, unsigned b1) {
    asm volatile(
        "mma.sync.aligned.m16n8k16.row.col.f32.bf16.bf16.f32 "
        "{%0,%1,%2,%3},{%4,%5,%6,%7},{%8,%9},{%0,%1,%2,%3};\n"
        : "+f"(c[0]), "+f"(c[1]), "+f"(c[2]), "+f"(c[3])
        : "r"(a0), "r"(a1), "r"(a2), "r"(a3), "r"(b0), "r"(b1));
}

// ---------------- K0a: weights fp32 -> bf16 ----------------
__global__ void convw_kernel(const float* __restrict__ wq, const float* __restrict__ wk,
                             const float* __restrict__ wv, const float* __restrict__ wo) {
    int stride = gridDim.x * blockDim.x;
    int t0 = blockIdx.x * blockDim.x + threadIdx.x;
    const int WSZ = CCH*CCH;
    for (int i = t0; i < WSZ; i += stride) {
        g_W[i]         = f2bf(wq[i]);
        g_W[WSZ + i]   = f2bf(wk[i]);
        g_W[2*WSZ + i] = f2bf(wv[i]);
        g_W[3*WSZ + i] = f2bf(wo[i]);
    }
}

// ---------------- K0b: x [n][c][s] fp32 -> x^T [n][s][c] bf16 ----------------
__global__ void transpose_kernel(const float* __restrict__ x) {
    __shared__ float t[32][33];
    int n = blockIdx.z;
    int s0 = blockIdx.x * 32, c0 = blockIdx.y * 32;
    int tx = threadIdx.x, ty = threadIdx.y;   // 32 x 8
    const float* src = x + ((size_t)n*CCH + c0)*SSP + s0;
    #pragma unroll
    for (int k = 0; k < 4; k++)
        t[ty + 8*k][tx] = src[(size_t)(ty + 8*k)*SSP + tx];
    __syncthreads();
    unsigned short* dst = g_xT + ((size_t)n*SSP + s0)*CCH + c0;
    #pragma unroll
    for (int k = 0; k < 4; k++)
        dst[(size_t)(ty + 8*k)*CCH + tx] = f2bf(t[tx][ty + 8*k]);
}

// ---------------- K1/K3: tiled GEMM, all operands K-major (stride-512 rows) ----------------
#define GSTAGE 32768
#define G_SMEM (3*GSTAGE)
__global__ __launch_bounds__(256,2) void gemm_kernel(int phase,
        const float* __restrict__ bq, const float* __restrict__ bk,
        const float* __restrict__ bv, const float* __restrict__ bo,
        const float* __restrict__ x, const float* __restrict__ gamma,
        float* __restrict__ out) {
    extern __shared__ __align__(1024) unsigned char gsm[];
    unsigned smb = smem_u32(gsm);

    int which, n;
    if (phase == 0) { int z = blockIdx.z; which = z >> 1; n = z & 1; }
    else            { which = 3; n = blockIdx.z; }

    int tid = threadIdx.x;
    int sBase = blockIdx.x * 128;   // token-tile
    int oBase = blockIdx.y * 128;   // output-channel tile
    const unsigned short* xTn = g_xT + (size_t)n * SSP * CCH;
    const unsigned short* Am;
    const unsigned short* Bm;
    if (which <= 1) {
        Am = xTn + (size_t)sBase*CCH;
        Bm = g_W + (size_t)which*CCH*CCH + (size_t)oBase*CCH;
    } else if (which == 2) {
        Am = g_W + 2*(size_t)CCH*CCH + (size_t)oBase*CCH;
        Bm = xTn + (size_t)sBase*CCH;
    } else {
        Am = g_W + 3*(size_t)CCH*CCH + (size_t)oBase*CCH;
        Bm = g_Ot + (size_t)n*SSP*CCH + (size_t)sBase*CCH;
    }

    int warp = tid >> 5, lane = tid & 31, g = lane >> 2, qi = lane & 3;
    int wm = warp >> 1, wn = warp & 1;
    int lq  = (lane & 7) + 8*((lane >> 3) & 1);
    int lc  = 8*(lane >> 4);
    int lq2 = (lane & 7) + 8*(lane >> 4);
    int lc2 = 8*((lane >> 3) & 1);

    auto sw = [](int r, int k) -> unsigned {
        return (unsigned)(r*128 + ((2*k) ^ ((r & 7) << 4)));
    };

    float acc[2][8][4];
    #pragma unroll
    for (int a = 0; a < 2; a++)
        #pragma unroll
        for (int b = 0; b < 8; b++)
            #pragma unroll
            for (int c = 0; c < 4; c++) acc[a][b][c] = 0.f;

    auto stage = [&](int s) {
        unsigned ab = smb + (unsigned)(s % 3) * (unsigned)GSTAGE;
        unsigned bb = ab + 16384u;
        int kc = s * 64;
        #pragma unroll
        for (int j = 0; j < 4; j++) {
            int u = tid + j*256;
            int r = u >> 3, ck = (u & 7) * 8;
            cpasync16(ab + sw(r, ck), &Am[(size_t)r*CCH + kc + ck]);
            cpasync16(bb + sw(r, ck), &Bm[(size_t)r*CCH + kc + ck]);
        }
        cpcommit();
    };

    stage(0);
    stage(1);

    for (int s = 0; s < 8; s++) {
        if (s < 7) cpwait<1>(); else cpwait<0>();
        __syncthreads();
        if (s + 2 < 8) stage(s + 2);

        unsigned ab = smb + (unsigned)(s % 3) * (unsigned)GSTAGE;
        unsigned bb = ab + 16384u;
        #pragma unroll
        for (int ks = 0; ks < 4; ks++) {
            int k0 = ks * 16;
            unsigned af[2][4], bf[8][2];
            #pragma unroll
            for (int mt = 0; mt < 2; mt++)
                ldsm_x4(af[mt][0], af[mt][1], af[mt][2], af[mt][3],
                        ab + sw(wm*32 + mt*16 + lq, k0 + lc));
            #pragma unroll
            for (int ng = 0; ng < 4; ng++) {
                unsigned r0, r1, r2, r3;
                ldsm_x4(r0, r1, r2, r3,
                        bb + sw(wn*64 + ng*16 + lq2, k0 + lc2));
                bf[2*ng][0] = r0;  bf[2*ng][1] = r1;
                bf[2*ng+1][0] = r2; bf[2*ng+1][1] = r3;
            }
            #pragma unroll
            for (int mt = 0; mt < 2; mt++)
                #pragma unroll
                for (int nt = 0; nt < 8; nt++)
                    mma16816(acc[mt][nt], af[mt][0], af[mt][1], af[mt][2], af[mt][3],
                             bf[nt][0], bf[nt][1]);
        }
    }

    // ---------------- epilogue ----------------
    if (which <= 1) {
        const float* bias = (which == 0) ? bq : bk;
        unsigned short* dst = (which == 0) ? g_Qt : g_Kt;
        float qs = (which == 0) ? QSCALE : 1.0f;
        #pragma unroll
        for (int nt = 0; nt < 8; nt++) {
            int c = oBase + wn*64 + nt*8 + 2*qi;
            float b0 = bias[c], b1 = bias[c + 1];
            int h = c >> 6, d = c & 63;
            unsigned short* dh = dst + (size_t)(n*8 + h)*(SSP*HD) + d;
            #pragma unroll
            for (int mt = 0; mt < 2; mt++) {
                int r0 = sBase + wm*32 + mt*16 + g;
                *(unsigned*)&dh[(size_t) r0      *HD] =
                    pk2((acc[mt][nt][0] + b0)*qs, (acc[mt][nt][1] + b1)*qs);
                *(unsigned*)&dh[(size_t)(r0 + 8) *HD] =
                    pk2((acc[mt][nt][2] + b0)*qs, (acc[mt][nt][3] + b1)*qs);
            }
        }
    } else if (which == 2) {
        #pragma unroll
        for (int mt = 0; mt < 2; mt++) {
            int o0 = oBase + wm*32 + mt*16 + g;
            int o1 = o0 + 8;
            float b0 = bv[o0], b1 = bv[o1];
            #pragma unroll
            for (int nt = 0; nt < 8; nt++) {
                int s = sBase + wn*64 + nt*8 + 2*qi;
                unsigned short* d0p = g_Vc + ((size_t)n*CCH + o0) * SSP;
                unsigned short* d1p = g_Vc + ((size_t)n*CCH + o1) * SSP;
                *(unsigned*)&d0p[s] = pk2(acc[mt][nt][0] + b0, acc[mt][nt][1] + b0);
                *(unsigned*)&d1p[s] = pk2(acc[mt][nt][2] + b1, acc[mt][nt][3] + b1);
            }
        }
    } else {
        float gm = gamma[0];
        #pragma unroll
        for (int mt = 0; mt < 2; mt++) {
            int o0 = oBase + wm*32 + mt*16 + g;
            int o1 = o0 + 8;
            float b0 = bo[o0], b1 = bo[o1];
            #pragma unroll
            for (int nt = 0; nt < 8; nt++) {
                int s = sBase + wn*64 + nt*8 + 2*qi;
                size_t i0 = ((size_t)n*CCH + o0) * SSP + s;
                size_t i1 = ((size_t)n*CCH + o1) * SSP + s;
                out[i0]     = gm * (acc[mt][nt][0] + b0) + x[i0];
                out[i0 + 1] = gm * (acc[mt][nt][1] + b0) + x[i0 + 1];
                out[i1]     = gm * (acc[mt][nt][2] + b1) + x[i1];
                out[i1 + 1] = gm * (acc[mt][nt][3] + b1) + x[i1 + 1];
            }
        }
    }
}

// ---------------- K2: flash attention, Br=128, Bc=128/stage ----------------
// 512 CTAs, 1D warp split (16 rows/warp). Q fragments hoisted into registers
// (loaded once at it==0 — Q smem is never overwritten before the epilogue).
// Q pre-scaled (log2 units); no running max; row sums via ones-MMA.
#define FL_SMEM (16384 + 3*32768)
__global__ __launch_bounds__(256,2) void flash_kernel() {
    extern __shared__ __align__(1024) unsigned char smarr[];
    unsigned qb = smem_u32(smarr);
    unsigned kv = qb + 16384;   // stage s at kv + (s%3)*32768: [K0 8K | K1 8K | V0 8K | V1 8K]

    int tid = threadIdx.x;
    int nh = blockIdx.y;            // n*8 + h
    int s0 = blockIdx.x * 128;
    const unsigned short* Qg = g_Qt + (size_t)nh * (SSP*HD);
    const unsigned short* Kg = g_Kt + (size_t)nh * (SSP*HD);
    const unsigned short* Vg = g_Vc + (size_t)nh * (HD*SSP);

    int warp = tid >> 5, lane = tid & 31, g = lane >> 2, qi = lane & 3;
    int mrow = warp * 16;
    int lq  = (lane & 7) + 8*((lane >> 3) & 1);
    int lc  = 8*(lane >> 4);
    int lq2 = (lane & 7) + 8*(lane >> 4);
    int lc2 = 8*((lane >> 3) & 1);

    auto sw = [](int row, int ch) -> unsigned {
        return (unsigned)(row*128 + ((ch*2) ^ ((row & 7) << 4)));
    };

    auto stageld = [&](int s) {
        unsigned sb = kv + (unsigned)(s % 3) * 32768u;
        int t0 = s * 128;
        #pragma unroll
        for (int r = 0; r < 2; r++) {
            int u = tid + r*256; int row = u >> 3, c = (u & 7) * 8;
            cpasync16(sb +          sw(row, c), &Kg[(size_t)(t0 + row)*HD + c]);
            cpasync16(sb + 8192u  + sw(row, c), &Kg[(size_t)(t0 + 64 + row)*HD + c]);
            cpasync16(sb + 16384u + sw(row, c), &Vg[(size_t)row*SSP + t0 + c]);
            cpasync16(sb + 24576u + sw(row, c), &Vg[(size_t)row*SSP + t0 + 64 + c]);
        }
        cpcommit();
    };

    // prologue: Q + stage0 in group 0, stage1 in group 1
    #pragma unroll
    for (int r = 0; r < 4; r++) {
        int u = tid + r*256; int row = u >> 3, c = (u & 7) * 8;
        cpasync16(qb + sw(row, c), &Qg[(size_t)(s0 + row)*HD + c]);
    }
    stageld(0);
    stageld(1);

    float lsum[4];
    lsum[0] = lsum[1] = lsum[2] = lsum[3] = 0.f;
    float o[8][4];
    #pragma unroll
    for (int a = 0; a < 8; a++)
        #pragma unroll
        for (int b = 0; b < 4; b++) o[a][b] = 0.f;

    unsigned qf[4][4];   // Q fragments, loaded once (16 regs, persistent)

    for (int it = 0; it < 32; it++) {
        unsigned sb = kv + (unsigned)(((unsigned)it) % 3u) * 32768u;
        if (it < 31) cpwait<1>(); else cpwait<0>();
        __syncthreads();
        if (it == 0) {
            // Q commit-group retired by the first wait; load fragments once
            #pragma unroll
            for (int kk = 0; kk < 4; kk++)
                ldsm_x4(qf[kk][0], qf[kk][1], qf[kk][2], qf[kk][3],
                        qb + sw(mrow + lq, kk*16 + lc));
        }
        if (it + 2 < 32) stageld(it + 2);

        #pragma unroll
        for (int hlf = 0; hlf < 2; hlf++) {
            unsigned kb = sb + (unsigned)hlf * 8192u;
            unsigned vb = sb + 16384u + (unsigned)hlf * 8192u;

            // S = Q @ K^T (log2 units)
            float sc[8][4];
            #pragma unroll
            for (int a = 0; a < 8; a++)
                #pragma unroll
                for (int b = 0; b < 4; b++) sc[a][b] = 0.f;
            #pragma unroll
            for (int kk = 0; kk < 4; kk++) {
                #pragma unroll
                for (int ng = 0; ng < 4; ng++) {
                    unsigned r0, r1, r2, r3;
                    ldsm_x4(r0, r1, r2, r3, kb + sw(ng*16 + lq2, kk*16 + lc2));
                    mma16816(sc[2*ng],     qf[kk][0], qf[kk][1], qf[kk][2], qf[kk][3], r0, r1);
                    mma16816(sc[2*ng + 1], qf[kk][0], qf[kk][1], qf[kk][2], qf[kk][3], r2, r3);
                }
            }

            // p = 2^s
            #pragma unroll
            for (int nt = 0; nt < 8; nt++) {
                sc[nt][0] = ex2(sc[nt][0]);
                sc[nt][1] = ex2(sc[nt][1]);
                sc[nt][2] = ex2(sc[nt][2]);
                sc[nt][3] = ex2(sc[nt][3]);
            }

            // O += P @ V ; row sums via ones-MMA
            #pragma unroll
            for (int kt = 0; kt < 4; kt++) {
                unsigned a0 = pk2(sc[2*kt    ][0], sc[2*kt    ][1]);
                unsigned a1 = pk2(sc[2*kt    ][2], sc[2*kt    ][3]);
                unsigned a2 = pk2(sc[2*kt + 1][0], sc[2*kt + 1][1]);
                unsigned a3 = pk2(sc[2*kt + 1][2], sc[2*kt + 1][3]);
                mma16816(lsum, a0, a1, a2, a3, ONES2, ONES2);
                #pragma unroll
                for (int ng = 0; ng < 4; ng++) {
                    unsigned r0, r1, r2, r3;
                    ldsm_x4(r0, r1, r2, r3, vb + sw(ng*16 + lq2, kt*16 + lc2));
                    mma16816(o[2*ng],     a0, a1, a2, a3, r0, r1);
                    mma16816(o[2*ng + 1], a0, a1, a2, a3, r2, r3);
                }
            }
        }
    }

    // every lane holds its two row sums directly
    float inv0 = 1.f / lsum[0], inv1 = 1.f / lsum[2];

    // finalize: direct token-major stores [n][s][c] (no transpose)
    int nn = nh >> 3, h = nh & 7;
    unsigned short* Og = g_Ot + ((size_t)nn*SSP + s0)*CCH + h*64;
    int r0w = mrow + g, r1w = mrow + g + 8;
    #pragma unroll
    for (int nt = 0; nt < 8; nt++) {
        int dv = nt*8 + 2*qi;
        *(unsigned*)&Og[(size_t)r0w*CCH + dv] = pk2(o[nt][0]*inv0, o[nt][1]*inv0);
        *(unsigned*)&Og[(size_t)r1w*CCH + dv] = pk2(o[nt][2]*inv1, o[nt][3]*inv1);
    }
}

// ---------------- launch ----------------
extern "C" void kernel_launch(void* const* d_in, const int* in_sizes, int n_in,
                              void* d_out, int out_size) {
    const float* x     = (const float*)d_in[0];
    const float* Wq    = (const float*)d_in[1];
    const float* bq    = (const float*)d_in[2];
    const float* Wk    = (const float*)d_in[3];
    const float* bk    = (const float*)d_in[4];
    const float* Wv    = (const float*)d_in[5];
    const float* bv    = (const float*)d_in[6];
    const float* Wo    = (const float*)d_in[7];
    const float* bo    = (const float*)d_in[8];
    const float* gamma = (const float*)d_in[9];
    float* out = (float*)d_out;

    cudaFuncSetAttribute(flash_kernel,
        cudaFuncAttributeMaxDynamicSharedMemorySize, FL_SMEM);
    cudaFuncSetAttribute(gemm_kernel,
        cudaFuncAttributeMaxDynamicSharedMemorySize, G_SMEM);

    convw_kernel<<<512, 256>>>(Wq, Wk, Wv, Wo);
    transpose_kernel<<<dim3(SSP/32, CCH/32, NB), dim3(32, 8)>>>(x);
    gemm_kernel<<<dim3(SSP/128, CCH/128, 6), 256, G_SMEM>>>(0, bq, bk, bv, bo, x, gamma, out);
    flash_kernel<<<dim3(SSP/128, NHTOT), 256, FL_SMEM>>>();
    gemm_kernel<<<dim3(SSP/128, CCH/128, NB), 256, G_SMEM>>>(1, bq, bk, bv, bo, x, gamma, out);
}